// round 1
// baseline (speedup 1.0000x reference)
#include <cuda_runtime.h>
#include <cstddef>

#define NA 120001
#define NB 260001
#define AF 133
#define BF 147
#define HD 256
#define MAXNB 6
#define NMOL 6000
#define APM 20

#define BM 128
#define BN 128
#define BK 8

// ---------------- scratch (device globals; no allocation allowed) ----------
__device__ float g_inp [(size_t)NB * HD];   // pre-activation of W_i GEMM
__device__ float g_msgA[(size_t)NB * HD];   // message ping
__device__ float g_msgB[(size_t)NB * HD];   // message pong
__device__ float g_amsg[(size_t)NA * HD];   // per-atom summed messages
__device__ float g_hid [(size_t)NA * HD];   // atom_hiddens

// ============================================================================
// GEMM 1: g_inp = f_bonds @ W_i ; g_msgA = relu(g_inp)
//   A = f_bonds [NB, 147] (unaligned rows -> scalar loads), B = W_i [147,256]
// ============================================================================
__global__ void __launch_bounds__(256, 2) gemm_i_kernel(
    const float* __restrict__ fB, const float* __restrict__ Wi)
{
    __shared__ float As[BK][BM];
    __shared__ float Bs[BK][BN];

    const int tid  = threadIdx.x;
    const int bm   = blockIdx.y * BM;
    const int bn   = blockIdx.x * BN;

    const int arow = tid >> 1;            // 0..127
    const int acol = (tid & 1) << 2;      // 0 or 4
    const int brow = tid >> 5;            // 0..7
    const int bcol = (tid & 31) << 2;     // 0..124

    const int grow   = bm + arow;
    const bool rowOK = grow < NB;

    const int tx = tid & 15, ty = tid >> 4;

    float acc[8][8];
#pragma unroll
    for (int i = 0; i < 8; i++)
#pragma unroll
        for (int j = 0; j < 8; j++) acc[i][j] = 0.f;

    for (int k0 = 0; k0 < BF; k0 += BK) {
#pragma unroll
        for (int i = 0; i < 4; i++) {
            int k = k0 + acol + i;
            float v = 0.f;
            if (rowOK && k < BF) v = fB[(size_t)grow * BF + k];
            As[acol + i][arow] = v;
        }
        {
            int kB = k0 + brow;
            float4 vb = make_float4(0.f, 0.f, 0.f, 0.f);
            if (kB < BF) vb = *(const float4*)(Wi + (size_t)kB * HD + bn + bcol);
            *(float4*)&Bs[brow][bcol] = vb;
        }
        __syncthreads();
#pragma unroll
        for (int k = 0; k < BK; k++) {
            float ra[8], rb[8];
#pragma unroll
            for (int i = 0; i < 8; i++) ra[i] = As[k][ty * 8 + i];
#pragma unroll
            for (int j = 0; j < 8; j++) rb[j] = Bs[k][tx * 8 + j];
#pragma unroll
            for (int i = 0; i < 8; i++)
#pragma unroll
                for (int j = 0; j < 8; j++) acc[i][j] += ra[i] * rb[j];
        }
        __syncthreads();
    }

#pragma unroll
    for (int i = 0; i < 8; i++) {
        int r = bm + ty * 8 + i;
        if (r >= NB) continue;
#pragma unroll
        for (int j = 0; j < 8; j += 4) {
            int c = bn + tx * 8 + j;
            float4 p;
            p.x = acc[i][j + 0]; p.y = acc[i][j + 1];
            p.z = acc[i][j + 2]; p.w = acc[i][j + 3];
            *(float4*)(g_inp + (size_t)r * HD + c) = p;
            float4 m;
            m.x = fmaxf(p.x, 0.f); m.y = fmaxf(p.y, 0.f);
            m.z = fmaxf(p.z, 0.f); m.w = fmaxf(p.w, 0.f);
            *(float4*)(g_msgA + (size_t)r * HD + c) = m;
        }
    }
}

// ============================================================================
// gather-sum: g_amsg[a] = sum_{j<6} msg[a2b[a][j]]
//   src==0 reads g_msgA, src==1 reads g_msgB. One thread per (atom, float4).
// ============================================================================
__global__ void __launch_bounds__(256) gather_sum_kernel(
    int src, const int* __restrict__ a2b)
{
    const float* __restrict__ msg = (src == 0) ? g_msgA : g_msgB;
    long long t = (long long)blockIdx.x * blockDim.x + threadIdx.x;
    if (t >= (long long)NA * (HD / 4)) return;
    int a = (int)(t >> 6);
    int c = (int)(t & 63);
    const int* nb = a2b + (size_t)a * MAXNB;
    float4 acc = make_float4(0.f, 0.f, 0.f, 0.f);
#pragma unroll
    for (int j = 0; j < MAXNB; j++) {
        int b = __ldg(nb + j);
        float4 v = ((const float4*)(msg + (size_t)b * HD))[c];
        acc.x += v.x; acc.y += v.y; acc.z += v.z; acc.w += v.w;
    }
    ((float4*)(g_amsg + (size_t)a * HD))[c] = acc;
}

// ============================================================================
// GEMM H: msgOut = relu(g_inp + (g_amsg[b2a[b]] - msgIn[b2revb[b]]) @ W_h)
//   Gather fused into A-tile load; epilogue fused. K = 256 (vectorized).
//   src==0: msgA -> msgB ; src==1: msgB -> msgA
// ============================================================================
__global__ void __launch_bounds__(256, 2) gemm_h_kernel(
    int src, const float* __restrict__ Wh,
    const int* __restrict__ b2a, const int* __restrict__ b2revb)
{
    const float* __restrict__ msgIn  = (src == 0) ? g_msgA : g_msgB;
    float*       __restrict__ msgOut = (src == 0) ? g_msgB : g_msgA;

    __shared__ float As[BK][BM];
    __shared__ float Bs[BK][BN];

    const int tid  = threadIdx.x;
    const int bm   = blockIdx.y * BM;
    const int bn   = blockIdx.x * BN;

    const int arow = tid >> 1;
    const int acol = (tid & 1) << 2;
    const int brow = tid >> 5;
    const int bcol = (tid & 31) << 2;

    const int grow   = bm + arow;
    const bool rowOK = grow < NB;
    const float* pA1 = nullptr;
    const float* pA2 = nullptr;
    if (rowOK) {
        pA1 = g_amsg + (size_t)__ldg(b2a + grow)   * HD;
        pA2 = msgIn  + (size_t)__ldg(b2revb + grow) * HD;
    }

    const int tx = tid & 15, ty = tid >> 4;

    float acc[8][8];
#pragma unroll
    for (int i = 0; i < 8; i++)
#pragma unroll
        for (int j = 0; j < 8; j++) acc[i][j] = 0.f;

    for (int k0 = 0; k0 < HD; k0 += BK) {
        float4 va = make_float4(0.f, 0.f, 0.f, 0.f);
        if (rowOK) {
            float4 v1 = *(const float4*)(pA1 + k0 + acol);
            float4 v2 = *(const float4*)(pA2 + k0 + acol);
            va.x = v1.x - v2.x; va.y = v1.y - v2.y;
            va.z = v1.z - v2.z; va.w = v1.w - v2.w;
        }
        As[acol + 0][arow] = va.x;
        As[acol + 1][arow] = va.y;
        As[acol + 2][arow] = va.z;
        As[acol + 3][arow] = va.w;

        *(float4*)&Bs[brow][bcol] =
            *(const float4*)(Wh + (size_t)(k0 + brow) * HD + bn + bcol);
        __syncthreads();
#pragma unroll
        for (int k = 0; k < BK; k++) {
            float ra[8], rb[8];
#pragma unroll
            for (int i = 0; i < 8; i++) ra[i] = As[k][ty * 8 + i];
#pragma unroll
            for (int j = 0; j < 8; j++) rb[j] = Bs[k][tx * 8 + j];
#pragma unroll
            for (int i = 0; i < 8; i++)
#pragma unroll
                for (int j = 0; j < 8; j++) acc[i][j] += ra[i] * rb[j];
        }
        __syncthreads();
    }

#pragma unroll
    for (int i = 0; i < 8; i++) {
        int r = bm + ty * 8 + i;
        if (r >= NB) continue;
#pragma unroll
        for (int j = 0; j < 8; j += 4) {
            int c = bn + tx * 8 + j;
            float4 ip = *(const float4*)(g_inp + (size_t)r * HD + c);
            float4 o;
            o.x = fmaxf(ip.x + acc[i][j + 0], 0.f);
            o.y = fmaxf(ip.y + acc[i][j + 1], 0.f);
            o.z = fmaxf(ip.z + acc[i][j + 2], 0.f);
            o.w = fmaxf(ip.w + acc[i][j + 3], 0.f);
            *(float4*)(msgOut + (size_t)r * HD + c) = o;
        }
    }
}

// ============================================================================
// GEMM O: g_hid = relu([f_atoms | g_amsg] @ W_o + b_o)   (concat fused in A)
//   K = 389 (133 + 256), scalar A loads (unaligned), B = W_o [389,256]
// ============================================================================
__global__ void __launch_bounds__(256, 2) gemm_o_kernel(
    const float* __restrict__ fA, const float* __restrict__ Wo,
    const float* __restrict__ bo)
{
    __shared__ float As[BK][BM];
    __shared__ float Bs[BK][BN];

    const int tid  = threadIdx.x;
    const int bm   = blockIdx.y * BM;
    const int bn   = blockIdx.x * BN;

    const int arow = tid >> 1;
    const int acol = (tid & 1) << 2;
    const int brow = tid >> 5;
    const int bcol = (tid & 31) << 2;

    const int grow   = bm + arow;
    const bool rowOK = grow < NA;

    const int tx = tid & 15, ty = tid >> 4;
    const int KT = AF + HD;   // 389

    float acc[8][8];
#pragma unroll
    for (int i = 0; i < 8; i++)
#pragma unroll
        for (int j = 0; j < 8; j++) acc[i][j] = 0.f;

    for (int k0 = 0; k0 < KT; k0 += BK) {
#pragma unroll
        for (int i = 0; i < 4; i++) {
            int k = k0 + acol + i;
            float v = 0.f;
            if (rowOK) {
                if (k < AF)      v = fA[(size_t)grow * AF + k];
                else if (k < KT) v = g_amsg[(size_t)grow * HD + (k - AF)];
            }
            As[acol + i][arow] = v;
        }
        {
            int kB = k0 + brow;
            float4 vb = make_float4(0.f, 0.f, 0.f, 0.f);
            if (kB < KT) vb = *(const float4*)(Wo + (size_t)kB * HD + bn + bcol);
            *(float4*)&Bs[brow][bcol] = vb;
        }
        __syncthreads();
#pragma unroll
        for (int k = 0; k < BK; k++) {
            float ra[8], rb[8];
#pragma unroll
            for (int i = 0; i < 8; i++) ra[i] = As[k][ty * 8 + i];
#pragma unroll
            for (int j = 0; j < 8; j++) rb[j] = Bs[k][tx * 8 + j];
#pragma unroll
            for (int i = 0; i < 8; i++)
#pragma unroll
                for (int j = 0; j < 8; j++) acc[i][j] += ra[i] * rb[j];
        }
        __syncthreads();
    }

#pragma unroll
    for (int i = 0; i < 8; i++) {
        int r = bm + ty * 8 + i;
        if (r >= NA) continue;
#pragma unroll
        for (int j = 0; j < 8; j += 4) {
            int c = bn + tx * 8 + j;
            float4 bb = *(const float4*)(bo + c);
            float4 o;
            o.x = fmaxf(acc[i][j + 0] + bb.x, 0.f);
            o.y = fmaxf(acc[i][j + 1] + bb.y, 0.f);
            o.z = fmaxf(acc[i][j + 2] + bb.z, 0.f);
            o.w = fmaxf(acc[i][j + 3] + bb.w, 0.f);
            *(float4*)(g_hid + (size_t)r * HD + c) = o;
        }
    }
}

// ============================================================================
// mol mean: out[m, j] = mean_{a<20} g_hid[1 + m*20 + a, j]
// ============================================================================
__global__ void __launch_bounds__(256) mol_mean_kernel(float* __restrict__ out)
{
    int t = blockIdx.x * blockDim.x + threadIdx.x;
    if (t >= NMOL * HD) return;
    int m = t / HD, j = t % HD;
    const float* base = g_hid + (size_t)(1 + m * APM) * HD + j;
    float s = 0.f;
#pragma unroll
    for (int a = 0; a < APM; a++) s += base[(size_t)a * HD];
    out[t] = s * (1.f / APM);
}

// ============================================================================
extern "C" void kernel_launch(void* const* d_in, const int* in_sizes, int n_in,
                              void* d_out, int out_size)
{
    const float* f_atoms = (const float*)d_in[0];
    const float* f_bonds = (const float*)d_in[1];
    const int*   a2b     = (const int*)d_in[2];
    const int*   b2a     = (const int*)d_in[3];
    const int*   b2revb  = (const int*)d_in[4];
    const float* W_i     = (const float*)d_in[5];
    const float* W_h     = (const float*)d_in[6];
    const float* W_o     = (const float*)d_in[7];
    const float* b_o     = (const float*)d_in[8];
    float* out = (float*)d_out;
    // depth=3, n_mols=6000, atoms_per_mol=20 are fixed by setup_inputs.

    dim3 blk(256);
    dim3 gI(HD / BN, (NB + BM - 1) / BM);
    dim3 gH(HD / BN, (NB + BM - 1) / BM);
    dim3 gO(HD / BN, (NA + BM - 1) / BM);

    long long gsT = (long long)NA * (HD / 4);
    int gsBlocks  = (int)((gsT + 255) / 256);
    int mmBlocks  = (NMOL * HD + 255) / 256;

    // inp + message(0)
    gemm_i_kernel<<<gI, blk>>>(f_bonds, W_i);
    // depth iteration 1: msgA -> msgB
    gather_sum_kernel<<<gsBlocks, blk>>>(0, a2b);
    gemm_h_kernel<<<gH, blk>>>(0, W_h, b2a, b2revb);
    // depth iteration 2: msgB -> msgA
    gather_sum_kernel<<<gsBlocks, blk>>>(1, a2b);
    gemm_h_kernel<<<gH, blk>>>(1, W_h, b2a, b2revb);
    // final aggregation over msgA
    gather_sum_kernel<<<gsBlocks, blk>>>(0, a2b);
    // readout
    gemm_o_kernel<<<gO, blk>>>(f_atoms, W_o, b_o);
    mol_mean_kernel<<<mmBlocks, blk>>>(out);
}

// round 2
// speedup vs baseline: 1.0082x; 1.0082x over previous
#include <cuda_runtime.h>
#include <cstddef>

#define NA 120001
#define NB 260001
#define AF 133
#define BF 147
#define HD 256
#define MAXNB 6
#define NMOL 6000
#define APM 20

#define BM 128
#define BN 128
#define BK 8

typedef unsigned long long u64;

// ---------------- scratch (device globals; no allocation allowed) ----------
__device__ float g_inp [(size_t)NB * HD];   // pre-activation of W_i GEMM
__device__ float g_msgA[(size_t)NB * HD];   // message ping
__device__ float g_msgB[(size_t)NB * HD];   // message pong
__device__ float g_amsg[(size_t)NA * HD];   // per-atom summed messages
__device__ float g_hid [(size_t)NA * HD];   // atom_hiddens

// ---------------- packed f32x2 helpers (FFMA2 path; exact fp32 numerics) ---
__device__ __forceinline__ u64 pack_dup(float v) {
    u64 r;
    asm("mov.b64 %0, {%1,%2};" : "=l"(r) : "f"(v), "f"(v));
    return r;
}
__device__ __forceinline__ u64 fma2(u64 a, u64 b, u64 c) {
    u64 d;
    asm("fma.rn.f32x2 %0, %1, %2, %3;" : "=l"(d) : "l"(a), "l"(b), "l"(c));
    return d;
}
__device__ __forceinline__ float2 unpack2(u64 v) {
    float2 f;
    asm("mov.b64 {%0,%1}, %2;" : "=f"(f.x), "=f"(f.y) : "l"(v));
    return f;
}

// Shared 8x8 microkernel step on packed accumulators acc2[8][4]
// (j packed in pairs). As row is contiguous in M, Bs row contiguous in N.
#define MICRO_K_STEP(As, Bs, k, ty, tx, acc2)                                  \
    {                                                                          \
        float4 a0 = *(const float4*)&As[k][(ty) * 8 + 0];                      \
        float4 a1 = *(const float4*)&As[k][(ty) * 8 + 4];                      \
        const u64* bp = (const u64*)&Bs[k][(tx) * 8];                          \
        u64 rb0 = bp[0], rb1 = bp[1], rb2 = bp[2], rb3 = bp[3];                \
        u64 ra[8];                                                             \
        ra[0] = pack_dup(a0.x); ra[1] = pack_dup(a0.y);                        \
        ra[2] = pack_dup(a0.z); ra[3] = pack_dup(a0.w);                        \
        ra[4] = pack_dup(a1.x); ra[5] = pack_dup(a1.y);                        \
        ra[6] = pack_dup(a1.z); ra[7] = pack_dup(a1.w);                        \
        _Pragma("unroll")                                                      \
        for (int i = 0; i < 8; i++) {                                          \
            acc2[i][0] = fma2(ra[i], rb0, acc2[i][0]);                         \
            acc2[i][1] = fma2(ra[i], rb1, acc2[i][1]);                         \
            acc2[i][2] = fma2(ra[i], rb2, acc2[i][2]);                         \
            acc2[i][3] = fma2(ra[i], rb3, acc2[i][3]);                         \
        }                                                                      \
    }

// ============================================================================
// GEMM 1: g_inp = f_bonds @ W_i ; g_msgA = relu(g_inp)
// ============================================================================
__global__ void __launch_bounds__(256, 2) gemm_i_kernel(
    const float* __restrict__ fB, const float* __restrict__ Wi)
{
    __shared__ float As[BK][BM];
    __shared__ float Bs[BK][BN];

    const int tid  = threadIdx.x;
    const int bm   = blockIdx.y * BM;
    const int bn   = blockIdx.x * BN;

    const int arow = tid >> 1;            // 0..127
    const int acol = (tid & 1) << 2;      // 0 or 4
    const int brow = tid >> 5;            // 0..7
    const int bcol = (tid & 31) << 2;     // 0..124

    const int grow   = bm + arow;
    const bool rowOK = grow < NB;

    const int tx = tid & 15, ty = tid >> 4;

    u64 acc2[8][4];
#pragma unroll
    for (int i = 0; i < 8; i++)
#pragma unroll
        for (int j = 0; j < 4; j++) acc2[i][j] = 0ull;

    for (int k0 = 0; k0 < BF; k0 += BK) {
#pragma unroll
        for (int i = 0; i < 4; i++) {
            int k = k0 + acol + i;
            float v = 0.f;
            if (rowOK && k < BF) v = fB[(size_t)grow * BF + k];
            As[acol + i][arow] = v;
        }
        {
            int kB = k0 + brow;
            float4 vb = make_float4(0.f, 0.f, 0.f, 0.f);
            if (kB < BF) vb = *(const float4*)(Wi + (size_t)kB * HD + bn + bcol);
            *(float4*)&Bs[brow][bcol] = vb;
        }
        __syncthreads();
#pragma unroll
        for (int k = 0; k < BK; k++) MICRO_K_STEP(As, Bs, k, ty, tx, acc2);
        __syncthreads();
    }

#pragma unroll
    for (int i = 0; i < 8; i++) {
        int r = bm + ty * 8 + i;
        if (r >= NB) continue;
#pragma unroll
        for (int jj = 0; jj < 4; jj += 2) {
            int c = bn + tx * 8 + jj * 2;
            float2 v0 = unpack2(acc2[i][jj]);
            float2 v1 = unpack2(acc2[i][jj + 1]);
            float4 p = make_float4(v0.x, v0.y, v1.x, v1.y);
            *(float4*)(g_inp + (size_t)r * HD + c) = p;
            float4 m;
            m.x = fmaxf(p.x, 0.f); m.y = fmaxf(p.y, 0.f);
            m.z = fmaxf(p.z, 0.f); m.w = fmaxf(p.w, 0.f);
            *(float4*)(g_msgA + (size_t)r * HD + c) = m;
        }
    }
}

// ============================================================================
// gather-sum: g_amsg[a] = sum_{j<6} msg[a2b[a][j]]
// ============================================================================
__global__ void __launch_bounds__(256) gather_sum_kernel(
    int src, const int* __restrict__ a2b)
{
    const float* __restrict__ msg = (src == 0) ? g_msgA : g_msgB;
    long long t = (long long)blockIdx.x * blockDim.x + threadIdx.x;
    if (t >= (long long)NA * (HD / 4)) return;
    int a = (int)(t >> 6);
    int c = (int)(t & 63);
    const int* nb = a2b + (size_t)a * MAXNB;
    float4 acc = make_float4(0.f, 0.f, 0.f, 0.f);
#pragma unroll
    for (int j = 0; j < MAXNB; j++) {
        int b = __ldg(nb + j);
        float4 v = ((const float4*)(msg + (size_t)b * HD))[c];
        acc.x += v.x; acc.y += v.y; acc.z += v.z; acc.w += v.w;
    }
    ((float4*)(g_amsg + (size_t)a * HD))[c] = acc;
}

// ============================================================================
// GEMM H: msgOut = relu(g_inp + (g_amsg[b2a[b]] - msgIn[b2revb[b]]) @ W_h)
// ============================================================================
__global__ void __launch_bounds__(256, 2) gemm_h_kernel(
    int src, const float* __restrict__ Wh,
    const int* __restrict__ b2a, const int* __restrict__ b2revb)
{
    const float* __restrict__ msgIn  = (src == 0) ? g_msgA : g_msgB;
    float*       __restrict__ msgOut = (src == 0) ? g_msgB : g_msgA;

    __shared__ float As[BK][BM];
    __shared__ float Bs[BK][BN];

    const int tid  = threadIdx.x;
    const int bm   = blockIdx.y * BM;
    const int bn   = blockIdx.x * BN;

    const int arow = tid >> 1;
    const int acol = (tid & 1) << 2;
    const int brow = tid >> 5;
    const int bcol = (tid & 31) << 2;

    const int grow   = bm + arow;
    const bool rowOK = grow < NB;
    const float* pA1 = nullptr;
    const float* pA2 = nullptr;
    if (rowOK) {
        pA1 = g_amsg + (size_t)__ldg(b2a + grow)    * HD;
        pA2 = msgIn  + (size_t)__ldg(b2revb + grow) * HD;
    }

    const int tx = tid & 15, ty = tid >> 4;

    u64 acc2[8][4];
#pragma unroll
    for (int i = 0; i < 8; i++)
#pragma unroll
        for (int j = 0; j < 4; j++) acc2[i][j] = 0ull;

    for (int k0 = 0; k0 < HD; k0 += BK) {
        float4 va = make_float4(0.f, 0.f, 0.f, 0.f);
        if (rowOK) {
            float4 v1 = *(const float4*)(pA1 + k0 + acol);
            float4 v2 = *(const float4*)(pA2 + k0 + acol);
            va.x = v1.x - v2.x; va.y = v1.y - v2.y;
            va.z = v1.z - v2.z; va.w = v1.w - v2.w;
        }
        As[acol + 0][arow] = va.x;
        As[acol + 1][arow] = va.y;
        As[acol + 2][arow] = va.z;
        As[acol + 3][arow] = va.w;

        *(float4*)&Bs[brow][bcol] =
            *(const float4*)(Wh + (size_t)(k0 + brow) * HD + bn + bcol);
        __syncthreads();
#pragma unroll
        for (int k = 0; k < BK; k++) MICRO_K_STEP(As, Bs, k, ty, tx, acc2);
        __syncthreads();
    }

#pragma unroll
    for (int i = 0; i < 8; i++) {
        int r = bm + ty * 8 + i;
        if (r >= NB) continue;
#pragma unroll
        for (int jj = 0; jj < 4; jj += 2) {
            int c = bn + tx * 8 + jj * 2;
            float2 v0 = unpack2(acc2[i][jj]);
            float2 v1 = unpack2(acc2[i][jj + 1]);
            float4 ip = *(const float4*)(g_inp + (size_t)r * HD + c);
            float4 o;
            o.x = fmaxf(ip.x + v0.x, 0.f);
            o.y = fmaxf(ip.y + v0.y, 0.f);
            o.z = fmaxf(ip.z + v1.x, 0.f);
            o.w = fmaxf(ip.w + v1.y, 0.f);
            *(float4*)(msgOut + (size_t)r * HD + c) = o;
        }
    }
}

// ============================================================================
// GEMM O: g_hid = relu([f_atoms | g_amsg] @ W_o + b_o)   (concat fused in A)
// ============================================================================
__global__ void __launch_bounds__(256, 2) gemm_o_kernel(
    const float* __restrict__ fA, const float* __restrict__ Wo,
    const float* __restrict__ bo)
{
    __shared__ float As[BK][BM];
    __shared__ float Bs[BK][BN];

    const int tid  = threadIdx.x;
    const int bm   = blockIdx.y * BM;
    const int bn   = blockIdx.x * BN;

    const int arow = tid >> 1;
    const int acol = (tid & 1) << 2;
    const int brow = tid >> 5;
    const int bcol = (tid & 31) << 2;

    const int grow   = bm + arow;
    const bool rowOK = grow < NA;

    const int tx = tid & 15, ty = tid >> 4;
    const int KT = AF + HD;   // 389

    u64 acc2[8][4];
#pragma unroll
    for (int i = 0; i < 8; i++)
#pragma unroll
        for (int j = 0; j < 4; j++) acc2[i][j] = 0ull;

    for (int k0 = 0; k0 < KT; k0 += BK) {
#pragma unroll
        for (int i = 0; i < 4; i++) {
            int k = k0 + acol + i;
            float v = 0.f;
            if (rowOK) {
                if (k < AF)      v = fA[(size_t)grow * AF + k];
                else if (k < KT) v = g_amsg[(size_t)grow * HD + (k - AF)];
            }
            As[acol + i][arow] = v;
        }
        {
            int kB = k0 + brow;
            float4 vb = make_float4(0.f, 0.f, 0.f, 0.f);
            if (kB < KT) vb = *(const float4*)(Wo + (size_t)kB * HD + bn + bcol);
            *(float4*)&Bs[brow][bcol] = vb;
        }
        __syncthreads();
#pragma unroll
        for (int k = 0; k < BK; k++) MICRO_K_STEP(As, Bs, k, ty, tx, acc2);
        __syncthreads();
    }

#pragma unroll
    for (int i = 0; i < 8; i++) {
        int r = bm + ty * 8 + i;
        if (r >= NA) continue;
#pragma unroll
        for (int jj = 0; jj < 4; jj += 2) {
            int c = bn + tx * 8 + jj * 2;
            float2 v0 = unpack2(acc2[i][jj]);
            float2 v1 = unpack2(acc2[i][jj + 1]);
            float4 bb = *(const float4*)(bo + c);
            float4 o;
            o.x = fmaxf(v0.x + bb.x, 0.f);
            o.y = fmaxf(v0.y + bb.y, 0.f);
            o.z = fmaxf(v1.x + bb.z, 0.f);
            o.w = fmaxf(v1.y + bb.w, 0.f);
            *(float4*)(g_hid + (size_t)r * HD + c) = o;
        }
    }
}

// ============================================================================
// mol mean: out[m, j] = mean_{a<20} g_hid[1 + m*20 + a, j]
// ============================================================================
__global__ void __launch_bounds__(256) mol_mean_kernel(float* __restrict__ out)
{
    int t = blockIdx.x * blockDim.x + threadIdx.x;
    if (t >= NMOL * HD) return;
    int m = t / HD, j = t % HD;
    const float* base = g_hid + (size_t)(1 + m * APM) * HD + j;
    float s = 0.f;
#pragma unroll
    for (int a = 0; a < APM; a++) s += base[(size_t)a * HD];
    out[t] = s * (1.f / APM);
}

// ============================================================================
extern "C" void kernel_launch(void* const* d_in, const int* in_sizes, int n_in,
                              void* d_out, int out_size)
{
    const float* f_atoms = (const float*)d_in[0];
    const float* f_bonds = (const float*)d_in[1];
    const int*   a2b     = (const int*)d_in[2];
    const int*   b2a     = (const int*)d_in[3];
    const int*   b2revb  = (const int*)d_in[4];
    const float* W_i     = (const float*)d_in[5];
    const float* W_h     = (const float*)d_in[6];
    const float* W_o     = (const float*)d_in[7];
    const float* b_o     = (const float*)d_in[8];
    float* out = (float*)d_out;

    dim3 blk(256);
    dim3 gI(HD / BN, (NB + BM - 1) / BM);
    dim3 gH(HD / BN, (NB + BM - 1) / BM);
    dim3 gO(HD / BN, (NA + BM - 1) / BM);

    long long gsT = (long long)NA * (HD / 4);
    int gsBlocks  = (int)((gsT + 255) / 256);
    int mmBlocks  = (NMOL * HD + 255) / 256;

    gemm_i_kernel<<<gI, blk>>>(f_bonds, W_i);
    gather_sum_kernel<<<gsBlocks, blk>>>(0, a2b);
    gemm_h_kernel<<<gH, blk>>>(0, W_h, b2a, b2revb);
    gather_sum_kernel<<<gsBlocks, blk>>>(1, a2b);
    gemm_h_kernel<<<gH, blk>>>(1, W_h, b2a, b2revb);
    gather_sum_kernel<<<gsBlocks, blk>>>(0, a2b);
    gemm_o_kernel<<<gO, blk>>>(f_atoms, W_o, b_o);
    mol_mean_kernel<<<mmBlocks, blk>>>(out);
}

// round 4
// speedup vs baseline: 1.5572x; 1.5446x over previous
#include <cuda_runtime.h>
#include <cuda_bf16.h>
#include <cstdint>
#include <cstddef>

#define NA 120001
#define NB 260001
#define AF 133
#define BF 147
#define HD 256
#define MAXNB 6
#define NMOL 6000
#define APM 20

#define BMT 64            // M rows per CTA
#define BK  32            // K elements per chunk

#define KPAD_I 160
#define KPAD_H 256
#define KPAD_O 416

// SMEM layout (bytes). Row stride = 40 halves = 80 B (16B-aligned, ldmatrix
// conflict-free: (r*20)%32 distinct for r=0..7).
#define SM_A_HI 0
#define SM_A_LO 5120
#define SM_B_HI 10240
#define SM_B_LO 30720
#define SMEM_TOTAL 51200

typedef unsigned int u32;

// ---------------- scratch (device globals; no allocation allowed) ----------
__device__ float g_inp [(size_t)NB * HD];
__device__ float g_msgA[(size_t)NB * HD];
__device__ float g_msgB[(size_t)NB * HD];
__device__ float g_amsg[(size_t)NA * HD];
__device__ float g_hid [(size_t)NA * HD];

// prepacked transposed weights, bf16 hi/lo: [term][N=256][Kpad]
__device__ __nv_bfloat16 g_Bi[2][256 * KPAD_I];
__device__ __nv_bfloat16 g_Bh[2][256 * KPAD_H];
__device__ __nv_bfloat16 g_Bo[2][256 * KPAD_O];

// ---------------- helpers ---------------------------------------------------
__device__ __forceinline__ u32 smem_to_u32(const void* p) {
    u32 a;
    asm("{ .reg .u64 t; cvta.to.shared.u64 t, %1; cvt.u32.u64 %0, t; }"
        : "=r"(a) : "l"(p));
    return a;
}
__device__ __forceinline__ void ldsm_x4(u32& r0, u32& r1, u32& r2, u32& r3, u32 a) {
    asm volatile("ldmatrix.sync.aligned.m8n8.x4.shared.b16 {%0,%1,%2,%3}, [%4];"
                 : "=r"(r0), "=r"(r1), "=r"(r2), "=r"(r3) : "r"(a));
}
__device__ __forceinline__ void mma_bf16(float* c, const u32* a, const u32* b) {
    asm volatile(
        "mma.sync.aligned.m16n8k16.row.col.f32.bf16.bf16.f32 "
        "{%0,%1,%2,%3},{%4,%5,%6,%7},{%8,%9},{%0,%1,%2,%3};"
        : "+f"(c[0]), "+f"(c[1]), "+f"(c[2]), "+f"(c[3])
        : "r"(a[0]), "r"(a[1]), "r"(a[2]), "r"(a[3]), "r"(b[0]), "r"(b[1]));
}
__device__ __forceinline__ u32 pkh(__nv_bfloat16 a, __nv_bfloat16 b) {
    return (u32)__bfloat16_as_ushort(a) | ((u32)__bfloat16_as_ushort(b) << 16);
}

// ---------------- weight prepack: transpose + hi/lo split + zero pad -------
// sel: 0 = W_i [147,256]->Kpad 160, 1 = W_h [256,256], 2 = W_o [389,256]->416
__global__ void pack_w_kernel(const float* __restrict__ W, int sel)
{
    int KPAD = (sel == 0) ? KPAD_I : (sel == 1) ? KPAD_H : KPAD_O;
    __nv_bfloat16* imgHi = (sel == 0) ? g_Bi[0] : (sel == 1) ? g_Bh[0] : g_Bo[0];
    __nv_bfloat16* imgLo = (sel == 0) ? g_Bi[1] : (sel == 1) ? g_Bh[1] : g_Bo[1];
    int t = blockIdx.x * blockDim.x + threadIdx.x;
    if (t >= 256 * KPAD) return;
    int n = t / KPAD, kk = t % KPAD;
    int srck;
    if (sel == 0)      srck = (kk < BF) ? kk : -1;
    else if (sel == 1) srck = kk;
    else               srck = (kk < 160) ? (kk < AF ? kk : -1) : (AF + (kk - 160));
    float w = (srck >= 0) ? W[(size_t)srck * HD + n] : 0.f;
    __nv_bfloat16 hi = __float2bfloat16(w);
    __nv_bfloat16 lo = __float2bfloat16(w - __bfloat162float(hi));
    imgHi[(size_t)n * KPAD + kk] = hi;
    imgLo[(size_t)n * KPAD + kk] = lo;
}

// ---------------- unified mma.sync GEMM -------------------------------------
// MODE 0: g_inp = f_bonds @ W_i ; g_msgA = relu(g_inp)
// MODE 1: msgOut = relu(g_inp + (g_amsg[b2a] - msgIn[b2revb]) @ W_h)
// MODE 2: g_hid = relu([f_atoms | g_amsg] @ W_o + b_o)
template <int MODE>
__global__ void __launch_bounds__(256, 2) mma_gemm_kernel(
    const float* __restrict__ srcA,
    const int* __restrict__ b2a, const int* __restrict__ b2revb,
    const float* __restrict__ bo, int srcSel)
{
    constexpr int NCH   = (MODE == 0) ? 5 : (MODE == 1) ? 8 : 13;
    constexpr int KPAD  = (MODE == 0) ? KPAD_I : (MODE == 1) ? KPAD_H : KPAD_O;
    constexpr int Mrows = (MODE == 2) ? NA : NB;
    constexpr int KV    = (MODE == 0) ? BF : AF;
    constexpr int KSTR  = (MODE == 0) ? BF : AF;

    const float* __restrict__ msgIn  = (srcSel == 0) ? g_msgA : g_msgB;
    float*       __restrict__ msgOut = (srcSel == 0) ? g_msgB : g_msgA;
    const __nv_bfloat16* imgHi =
        (MODE == 0) ? g_Bi[0] : (MODE == 1) ? g_Bh[0] : g_Bo[0];
    const __nv_bfloat16* imgLo =
        (MODE == 0) ? g_Bi[1] : (MODE == 1) ? g_Bh[1] : g_Bo[1];

    extern __shared__ char smem[];
    const u32 sbase = smem_to_u32(smem);

    const int tid  = threadIdx.x;
    const int lane = tid & 31;
    const int wid  = tid >> 5;
    const int wm   = wid >> 2;        // 0..1
    const int wn   = wid & 3;         // 0..3
    const int bm   = blockIdx.x * BMT;

    // A-loader coords: 4 threads per row, 8 cols each
    const int arow = tid >> 2;
    const int acg  = tid & 3;
    const int agr  = bm + arow;
    const float* p1 = nullptr;
    const float* p2 = nullptr;
    if (MODE == 1 && agr < NB) {
        p1 = g_amsg + (size_t)__ldg(b2a + agr)    * HD;
        p2 = msgIn  + (size_t)__ldg(b2revb + agr) * HD;
    }

    // ldmatrix lane addressing
    const int alrow = (lane & 7) + ((lane & 8)  ? 8 : 0);
    const int alk   = (lane & 16) ? 8 : 0;
    const int blrow = (lane & 7) + ((lane & 16) ? 8 : 0);
    const int blk   = (lane & 8)  ? 8 : 0;

    float acc[2][8][4];
#pragma unroll
    for (int i = 0; i < 2; i++)
#pragma unroll
        for (int j = 0; j < 8; j++)
#pragma unroll
            for (int q = 0; q < 4; q++) acc[i][j][q] = 0.f;

    for (int ch = 0; ch < NCH; ch++) {
        __syncthreads();   // protect SMEM until all warps finished prior chunk

        // ---- B chunk copy: thread t copies row t (64 B hi + 64 B lo) ----
        {
            const uint4* sh = (const uint4*)(imgHi + (size_t)tid * KPAD + ch * BK);
            const uint4* sl = (const uint4*)(imgLo + (size_t)tid * KPAD + ch * BK);
            uint4* dh = (uint4*)(smem + SM_B_HI + tid * 80);
            uint4* dl = (uint4*)(smem + SM_B_LO + tid * 80);
#pragma unroll
            for (int i = 0; i < 4; i++) { dh[i] = sh[i]; dl[i] = sl[i]; }
        }

        // ---- A chunk: gather fp32, split to bf16 hi/lo ----
        {
            float v[8];
            const bool vec = (MODE == 1) || (MODE == 2 && ch >= 5);
            if (vec) {
                float4 x1 = make_float4(0.f, 0.f, 0.f, 0.f), x2 = x1;
                if (agr < Mrows) {
                    if (MODE == 1) {
                        int off = ch * BK + acg * 8;
                        float4 a1 = *(const float4*)(p1 + off);
                        float4 b1 = *(const float4*)(p2 + off);
                        float4 a2 = *(const float4*)(p1 + off + 4);
                        float4 b2 = *(const float4*)(p2 + off + 4);
                        x1 = make_float4(a1.x - b1.x, a1.y - b1.y,
                                         a1.z - b1.z, a1.w - b1.w);
                        x2 = make_float4(a2.x - b2.x, a2.y - b2.y,
                                         a2.z - b2.z, a2.w - b2.w);
                    } else {
                        int off = (ch - 5) * BK + acg * 8;
                        const float* p = g_amsg + (size_t)agr * HD + off;
                        x1 = *(const float4*)(p);
                        x2 = *(const float4*)(p + 4);
                    }
                }
                v[0] = x1.x; v[1] = x1.y; v[2] = x1.z; v[3] = x1.w;
                v[4] = x2.x; v[5] = x2.y; v[6] = x2.z; v[7] = x2.w;
            } else {
#pragma unroll
                for (int j = 0; j < 8; j++) {
                    int k = ch * BK + acg * 8 + j;
                    v[j] = (agr < Mrows && k < KV)
                           ? __ldg(srcA + (size_t)agr * KSTR + k) : 0.f;
                }
            }
            __nv_bfloat16 h[8];
#pragma unroll
            for (int j = 0; j < 8; j++) h[j] = __float2bfloat16(v[j]);
            uint4 uh;
            uh.x = pkh(h[0], h[1]); uh.y = pkh(h[2], h[3]);
            uh.z = pkh(h[4], h[5]); uh.w = pkh(h[6], h[7]);
            *(uint4*)(smem + SM_A_HI + arow * 80 + acg * 16) = uh;
#pragma unroll
            for (int j = 0; j < 8; j++)
                h[j] = __float2bfloat16(v[j] - __bfloat162float(h[j]));
            uint4 ul;
            ul.x = pkh(h[0], h[1]); ul.y = pkh(h[2], h[3]);
            ul.z = pkh(h[4], h[5]); ul.w = pkh(h[6], h[7]);
            *(uint4*)(smem + SM_A_LO + arow * 80 + acg * 16) = ul;
        }

        __syncthreads();

        // ---- compute: 2 k16-steps ----
#pragma unroll
        for (int s = 0; s < 2; s++) {
            const int kb = s * 16;
            u32 ah[2][4], al[2][4];
#pragma unroll
            for (int mi = 0; mi < 2; mi++) {
                u32 ra = (wm * 32 + mi * 16 + alrow) * 80 + (kb + alk) * 2;
                ldsm_x4(ah[mi][0], ah[mi][1], ah[mi][2], ah[mi][3],
                        sbase + SM_A_HI + ra);
                ldsm_x4(al[mi][0], al[mi][1], al[mi][2], al[mi][3],
                        sbase + SM_A_LO + ra);
            }
#pragma unroll
            for (int nh = 0; nh < 2; nh++) {
                const int n0 = wn * 64 + nh * 32;
                u32 bh[4][2], bl[4][2];
                u32 rb0 = (n0 + blrow) * 80 + (kb + blk) * 2;
                u32 rb1 = (n0 + 16 + blrow) * 80 + (kb + blk) * 2;
                ldsm_x4(bh[0][0], bh[0][1], bh[1][0], bh[1][1], sbase + SM_B_HI + rb0);
                ldsm_x4(bh[2][0], bh[2][1], bh[3][0], bh[3][1], sbase + SM_B_HI + rb1);
                ldsm_x4(bl[0][0], bl[0][1], bl[1][0], bl[1][1], sbase + SM_B_LO + rb0);
                ldsm_x4(bl[2][0], bl[2][1], bl[3][0], bl[3][1], sbase + SM_B_LO + rb1);
#pragma unroll
                for (int mi = 0; mi < 2; mi++)
#pragma unroll
                    for (int nt = 0; nt < 4; nt++) {
                        float* c = acc[mi][nh * 4 + nt];
                        mma_bf16(c, ah[mi], bh[nt]);   // hi*hi
                        mma_bf16(c, ah[mi], bl[nt]);   // hi*lo
                        mma_bf16(c, al[mi], bh[nt]);   // lo*hi
                    }
            }
        }
    }

    // ---- epilogue (fused) ----
#pragma unroll
    for (int mi = 0; mi < 2; mi++) {
        int r0 = bm + wm * 32 + mi * 16 + (lane >> 2);
#pragma unroll
        for (int nj = 0; nj < 8; nj++) {
            int cc = wn * 64 + nj * 8 + (lane & 3) * 2;
#pragma unroll
            for (int half = 0; half < 2; half++) {
                int r = r0 + half * 8;
                if (r >= Mrows) continue;
                float vx = acc[mi][nj][half * 2 + 0];
                float vy = acc[mi][nj][half * 2 + 1];
                size_t o = (size_t)r * HD + cc;
                if (MODE == 0) {
                    *(float2*)(g_inp + o)  = make_float2(vx, vy);
                    *(float2*)(g_msgA + o) = make_float2(fmaxf(vx, 0.f),
                                                         fmaxf(vy, 0.f));
                } else if (MODE == 1) {
                    float2 ip = *(const float2*)(g_inp + o);
                    *(float2*)(msgOut + o) = make_float2(fmaxf(ip.x + vx, 0.f),
                                                         fmaxf(ip.y + vy, 0.f));
                } else {
                    float2 bb = *(const float2*)(bo + cc);
                    *(float2*)(g_hid + o) = make_float2(fmaxf(vx + bb.x, 0.f),
                                                        fmaxf(vy + bb.y, 0.f));
                }
            }
        }
    }
}

// ============================================================================
// gather-sum: g_amsg[a] = sum_{j<6} msg[a2b[a][j]]
// ============================================================================
__global__ void __launch_bounds__(256) gather_sum_kernel(
    int src, const int* __restrict__ a2b)
{
    const float* __restrict__ msg = (src == 0) ? g_msgA : g_msgB;
    long long t = (long long)blockIdx.x * blockDim.x + threadIdx.x;
    if (t >= (long long)NA * (HD / 4)) return;
    int a = (int)(t >> 6);
    int c = (int)(t & 63);
    const int* nb = a2b + (size_t)a * MAXNB;
    float4 acc = make_float4(0.f, 0.f, 0.f, 0.f);
#pragma unroll
    for (int j = 0; j < MAXNB; j++) {
        int b = __ldg(nb + j);
        float4 v = ((const float4*)(msg + (size_t)b * HD))[c];
        acc.x += v.x; acc.y += v.y; acc.z += v.z; acc.w += v.w;
    }
    ((float4*)(g_amsg + (size_t)a * HD))[c] = acc;
}

// ============================================================================
// mol mean
// ============================================================================
__global__ void __launch_bounds__(256) mol_mean_kernel(float* __restrict__ out)
{
    int t = blockIdx.x * blockDim.x + threadIdx.x;
    if (t >= NMOL * HD) return;
    int m = t / HD, j = t % HD;
    const float* base = g_hid + (size_t)(1 + m * APM) * HD + j;
    float s = 0.f;
#pragma unroll
    for (int a = 0; a < APM; a++) s += base[(size_t)a * HD];
    out[t] = s * (1.f / APM);
}

// ============================================================================
extern "C" void kernel_launch(void* const* d_in, const int* in_sizes, int n_in,
                              void* d_out, int out_size)
{
    const float* f_atoms = (const float*)d_in[0];
    const float* f_bonds = (const float*)d_in[1];
    const int*   a2b     = (const int*)d_in[2];
    const int*   b2a     = (const int*)d_in[3];
    const int*   b2revb  = (const int*)d_in[4];
    const float* W_i     = (const float*)d_in[5];
    const float* W_h     = (const float*)d_in[6];
    const float* W_o     = (const float*)d_in[7];
    const float* b_o     = (const float*)d_in[8];
    float* out = (float*)d_out;

    cudaFuncSetAttribute(mma_gemm_kernel<0>,
                         cudaFuncAttributeMaxDynamicSharedMemorySize, SMEM_TOTAL);
    cudaFuncSetAttribute(mma_gemm_kernel<1>,
                         cudaFuncAttributeMaxDynamicSharedMemorySize, SMEM_TOTAL);
    cudaFuncSetAttribute(mma_gemm_kernel<2>,
                         cudaFuncAttributeMaxDynamicSharedMemorySize, SMEM_TOTAL);

    // weight prepack (transpose + bf16 hi/lo split + pad)
    pack_w_kernel<<<(256 * KPAD_I + 255) / 256, 256>>>(W_i, 0);
    pack_w_kernel<<<(256 * KPAD_H + 255) / 256, 256>>>(W_h, 1);
    pack_w_kernel<<<(256 * KPAD_O + 255) / 256, 256>>>(W_o, 2);

    const int GB = (NB + BMT - 1) / BMT;   // 4063
    const int GA = (NA + BMT - 1) / BMT;   // 1876

    long long gsT = (long long)NA * (HD / 4);
    int gsBlocks  = (int)((gsT + 255) / 256);
    int mmBlocks  = (NMOL * HD + 255) / 256;

    mma_gemm_kernel<0><<<GB, 256, SMEM_TOTAL>>>(f_bonds, b2a, b2revb, b_o, 0);
    gather_sum_kernel<<<gsBlocks, 256>>>(0, a2b);
    mma_gemm_kernel<1><<<GB, 256, SMEM_TOTAL>>>(nullptr, b2a, b2revb, b_o, 0);
    gather_sum_kernel<<<gsBlocks, 256>>>(1, a2b);
    mma_gemm_kernel<1><<<GB, 256, SMEM_TOTAL>>>(nullptr, b2a, b2revb, b_o, 1);
    gather_sum_kernel<<<gsBlocks, 256>>>(0, a2b);
    mma_gemm_kernel<2><<<GA, 256, SMEM_TOTAL>>>(f_atoms, b2a, b2revb, b_o, 0);
    mol_mean_kernel<<<mmBlocks, 256>>>(out);
}